// round 3
// baseline (speedup 1.0000x reference)
#include <cuda_runtime.h>
#include <math.h>

#define BATCH  2
#define KPATCH 1600
#define DDIM   1024
#define CCLS   256
#define NBOX   32
#define PGRID  40
#define TARGET 560
#define BN     (BATCH*NBOX)            /* 64 */
#define NROWS  (BATCH*KPATCH + CCLS)   /* 3456 norm rows */
#define QSPLIT 4
#define DSPLIT 16                      /* 1024/64 */

// ---------------- scratch (static device globals; no allocation) ----------------
__device__ float g_fninv[BATCH*KPATCH];     // 1/||feats[b,k,:]||
__device__ float g_eninv[CCLS];             // 1/||emb[c,:]||
__device__ float g_vy[BN*PGRID];            // per-box summed weights (y axis)
__device__ float g_vx[BN*PGRID];            // per-box summed weights (x axis)
__device__ int   g_rect[BN*4];              // p0,p1,q0,q1 nonzero tap rectangle
__device__ float g_cntinv[BN];              // 1/(box pixel count)
__device__ float g_Qpart[QSPLIT*BN*DDIM];   // partial weighted feature sums
__device__ float g_Opart[DSPLIT*BN*CCLS];   // partial output GEMM sums

// Keys cubic, a = -0.5 (matches jax.image.resize 'bicubic'), fp32
__device__ __forceinline__ float cubicf(float x) {   // x >= 0
    if (x < 1.f) return ((1.5f*x - 2.5f)*x)*x + 1.f;
    if (x < 2.f) return ((-0.5f*x + 2.5f)*x - 4.f)*x + 2.f;
    return 0.f;
}

// normalized bicubic weight W[y][p] computed inline
__device__ __forceinline__ float wnorm(int y, int p) {
    float sf = (y + 0.5f) * (1.0f/14.0f) - 0.5f;
    float d  = fabsf(sf - (float)p);
    if (d >= 2.f) return 0.f;
    int i0 = (int)floorf(sf);
    float cs = 0.f;
    #pragma unroll
    for (int j = -1; j <= 2; ++j) {
        int ii = i0 + j;
        if (ii >= 0 && ii < PGRID) cs += cubicf(fabsf(sf - (float)ii));
    }
    return cubicf(d) / cs;
}

// ------- kernel 1: row L2 norms  +  per-box tap vectors (fused, independent) ----
__global__ void normbox_kernel(const float* __restrict__ feats,
                               const float* __restrict__ emb,
                               const int* __restrict__ boxes) {
    int blk = blockIdx.x;
    int t = threadIdx.x;
    if (blk < NROWS) {
        const float* p = (blk < BATCH*KPATCH)
                           ? feats + (size_t)blk * DDIM
                           : emb   + (size_t)(blk - BATCH*KPATCH) * DDIM;
        float4 v = ((const float4*)p)[t];
        float ss = v.x*v.x + v.y*v.y + v.z*v.z + v.w*v.w;
        #pragma unroll
        for (int o = 16; o; o >>= 1) ss += __shfl_xor_sync(0xffffffffu, ss, o);
        __shared__ float ws[8];
        if ((t & 31) == 0) ws[t >> 5] = ss;
        __syncthreads();
        if (t == 0) {
            float s = ws[0]+ws[1]+ws[2]+ws[3]+ws[4]+ws[5]+ws[6]+ws[7];
            float inv = 1.0f / sqrtf(s);
            if (blk < BATCH*KPATCH) g_fninv[blk] = inv;
            else                    g_eninv[blk - BATCH*KPATCH] = inv;
        }
    } else {
        // per-box branch: blk-NROWS = bn
        int bn = blk - NROWS;
        int x_min = boxes[bn*4+0], y_min = boxes[bn*4+1];
        int x_max = boxes[bn*4+2], y_max = boxes[bn*4+3];
        if (t < 2*PGRID) {
            int p, lo, hi;
            if (t < PGRID) { p = t;         lo = y_min; hi = y_max - 2; }
            else           { p = t - PGRID; lo = x_min; hi = x_max - 2; }
            float acc = 0.f;
            for (int y = lo; y <= hi; ++y) acc += wnorm(y, p);
            if (t < PGRID) g_vy[bn*PGRID + p] = acc;
            else           g_vx[bn*PGRID + p] = acc;
        }
        if (t == 0) {
            float sfl = (y_min + 0.5f) * (1.0f/14.0f) - 0.5f;
            float sfh = (y_max - 2 + 0.5f) * (1.0f/14.0f) - 0.5f;
            int p0 = max(0, (int)floorf(sfl) - 1);
            int p1 = min(PGRID - 1, (int)floorf(sfh) + 2);
            sfl = (x_min + 0.5f) * (1.0f/14.0f) - 0.5f;
            sfh = (x_max - 2 + 0.5f) * (1.0f/14.0f) - 0.5f;
            int q0 = max(0, (int)floorf(sfl) - 1);
            int q1 = min(PGRID - 1, (int)floorf(sfh) + 2);
            g_rect[bn*4+0] = p0; g_rect[bn*4+1] = p1;
            g_rect[bn*4+2] = q0; g_rect[bn*4+3] = q1;
            float cnt = (float)((y_max - 1 - y_min) * (x_max - 1 - x_min));
            g_cntinv[bn] = 1.0f / cnt;
        }
    }
}

// ---------------- kernel 2: Q[bn,d] = sum_k w[bn,k]/fn[b,k] * feats[b,k,d] ------
__global__ void __launch_bounds__(256) q_kernel(const float* __restrict__ feats) {
    int s  = blockIdx.x;       // 0..QSPLIT-1
    int bn = blockIdx.y;       // 0..63
    int b  = bn >> 5;
    int t  = threadIdx.x;

    __shared__ int   rect[4];
    __shared__ float vxs[16];
    if (t < 4) rect[t] = g_rect[bn*4+t];
    __syncthreads();
    int p0 = rect[0], p1 = rect[1], q0 = rect[2], q1 = rect[3];
    int nq = q1 - q0 + 1;      // <= 15
    if (t < 16) vxs[t] = (t < nq) ? g_vx[bn*PGRID + q0 + t] : 0.f;
    __syncthreads();

    int np  = p1 - p0 + 1;
    int plo = p0 + (np * s) / QSPLIT;
    int phi = p0 + (np * (s + 1)) / QSPLIT - 1;

    float4 acc = make_float4(0.f, 0.f, 0.f, 0.f);
    const float4* f4 = (const float4*)feats;

    for (int p = plo; p <= phi; ++p) {
        float wy = g_vy[bn*PGRID + p];
        int kbase = b*KPATCH + p*PGRID + q0;
        #pragma unroll
        for (int j = 0; j < 16; ++j) {
            int jj = min(j, nq - 1);                  // clamp address, weight is 0
            float w = wy * vxs[j] * g_fninv[kbase + jj];
            float4 f = f4[(size_t)(kbase + jj) * (DDIM/4) + t];
            acc.x += w * f.x; acc.y += w * f.y;
            acc.z += w * f.z; acc.w += w * f.w;
        }
    }
    ((float4*)g_Qpart)[(size_t)(s*BN + bn) * (DDIM/4) + t] = acc;
}

// ---------------- kernel 3: Opart = Q @ embT (64 x 1024 x 256, d-split) ---------
// Qs: [bn][dd] (reads are warp-broadcast). Es: [c][dd] with 68-float row stride
// (odd float4 stride -> phase-conflict-free LDS.128). Mainloop per 4-dd step:
// 8x LDS.128 (broadcast Q) + 1x LDS.128 (E) + 32 FFMA.
__global__ void __launch_bounds__(256) out_kernel(const float* __restrict__ emb) {
    __shared__ float Qs[BN * 64];      // [bn][dd]  16KB
    __shared__ float Es[32 * 68];      // [c][dd]   8.5KB, stride 68
    int c0 = blockIdx.x * 32;
    int d0 = blockIdx.y * 64;
    int t  = threadIdx.x;

    // load Q tile: sum QSPLIT partials, float4-vectorized (1024 float4 total)
    const float4* qp4 = (const float4*)g_Qpart;
    #pragma unroll
    for (int i = 0; i < 4; ++i) {
        int lin = i * 256 + t;                 // 0..1023
        int bn = lin >> 4, dd4 = lin & 15;     // dd4: float4 index within 64 dd
        float4 v = make_float4(0.f,0.f,0.f,0.f);
        #pragma unroll
        for (int sp = 0; sp < QSPLIT; ++sp) {
            float4 a = qp4[(size_t)(sp*BN + bn) * (DDIM/4) + (d0>>2) + dd4];
            v.x += a.x; v.y += a.y; v.z += a.z; v.w += a.w;
        }
        ((float4*)Qs)[bn*16 + dd4] = v;
    }
    // load E tile (512 float4), scale by 1/||emb_c||
    const float4* e4 = (const float4*)emb;
    #pragma unroll
    for (int i = 0; i < 2; ++i) {
        int lin = i * 256 + t;                 // 0..511
        int c = lin >> 4, dd4 = lin & 15;
        float s = g_eninv[c0 + c];
        float4 a = e4[(size_t)(c0 + c) * (DDIM/4) + (d0>>2) + dd4];
        a.x *= s; a.y *= s; a.z *= s; a.w *= s;
        *(float4*)&Es[c*68 + dd4*4] = a;
    }
    __syncthreads();

    int c = t & 31, g = t >> 5;        // 8 bn-groups of 8
    float acc[8] = {0,0,0,0,0,0,0,0};
    #pragma unroll
    for (int dd4 = 0; dd4 < 16; ++dd4) {
        float4 e = *(const float4*)&Es[c*68 + dd4*4];
        #pragma unroll
        for (int j = 0; j < 8; ++j) {
            float4 q = ((const float4*)Qs)[(g*8 + j)*16 + dd4];   // broadcast
            acc[j] += q.x*e.x + q.y*e.y + q.z*e.z + q.w*e.w;
        }
    }
    #pragma unroll
    for (int j = 0; j < 8; ++j)
        g_Opart[(blockIdx.y*BN + g*8 + j) * CCLS + c0 + c] = acc[j];
}

// ---------------- kernel 4: reduce d-split partials, apply 1/count -------------
__global__ void oreduce_kernel(float* __restrict__ out) {
    int o  = blockIdx.x * 256 + threadIdx.x;   // 16384 outputs
    int bn = o >> 8;
    float s = 0.f;
    #pragma unroll
    for (int i = 0; i < DSPLIT; ++i) s += g_Opart[i*BN*CCLS + o];
    out[o] = s * g_cntinv[bn];
}

// ---------------- launch --------------------------------------------------------
extern "C" void kernel_launch(void* const* d_in, const int* in_sizes, int n_in,
                              void* d_out, int out_size) {
    (void)in_sizes; (void)n_in; (void)out_size;
    const float* feats = (const float*)d_in[0];
    const float* emb   = (const float*)d_in[1];
    const int*   boxes = (const int*)d_in[2];
    float* out = (float*)d_out;

    normbox_kernel<<<NROWS + BN, 256>>>(feats, emb, boxes);
    q_kernel<<<dim3(QSPLIT, BN), 256>>>(feats);
    out_kernel<<<dim3(CCLS/32, DDIM/64), 256>>>(emb);
    oreduce_kernel<<<BN, 256>>>(out);
}

// round 4
// speedup vs baseline: 1.0269x; 1.0269x over previous
#include <cuda_runtime.h>
#include <math.h>

#define BATCH  2
#define KPATCH 1600
#define DDIM   1024
#define CCLS   256
#define NBOX   32
#define PGRID  40
#define TARGET 560
#define BN     (BATCH*NBOX)            /* 64 */
#define NROWS  (BATCH*KPATCH + CCLS)   /* 3456 norm rows */
#define QSPLIT 4

// ---------------- scratch (static device globals; no allocation) ----------------
__device__ float g_fninv[BATCH*KPATCH];     // 1/||feats[b,k,:]||
__device__ float g_eninv[CCLS];             // 1/||emb[c,:]||
__device__ float g_vy[BN*PGRID];            // per-box summed weights (y axis)
__device__ float g_vx[BN*PGRID];            // per-box summed weights (x axis)
__device__ int   g_rect[BN*4];              // p0,p1,q0,q1 nonzero tap rectangle
__device__ float g_cntinv[BN];              // 1/(box pixel count)
__device__ float g_Qpart[QSPLIT*BN*DDIM];   // partial weighted feature sums

// Keys cubic, a = -0.5 (matches jax.image.resize 'bicubic'), fp32
__device__ __forceinline__ float cubicf(float x) {   // x >= 0
    if (x < 1.f) return ((1.5f*x - 2.5f)*x)*x + 1.f;
    if (x < 2.f) return ((-0.5f*x + 2.5f)*x - 4.f)*x + 2.f;
    return 0.f;
}

// normalized bicubic weight W[y][p] — fast-divide version (MUFU.RCP, pipelined)
__device__ __forceinline__ float wnorm(int y, int p) {
    float sf = (y + 0.5f) * (1.0f/14.0f) - 0.5f;
    float d  = fabsf(sf - (float)p);
    if (d >= 2.f) return 0.f;
    int i0 = (int)floorf(sf);
    float cs = 0.f;
    #pragma unroll
    for (int j = -1; j <= 2; ++j) {
        int ii = i0 + j;
        if (ii >= 0 && ii < PGRID) cs += cubicf(fabsf(sf - (float)ii));
    }
    return __fdividef(cubicf(d), cs);
}

// ------- kernel 1: row L2 norms  +  per-box tap vectors (fused, independent) ----
__global__ void normbox_kernel(const float* __restrict__ feats,
                               const float* __restrict__ emb,
                               const int* __restrict__ boxes) {
    int blk = blockIdx.x;
    int t = threadIdx.x;
    if (blk < NROWS) {
        const float* p = (blk < BATCH*KPATCH)
                           ? feats + (size_t)blk * DDIM
                           : emb   + (size_t)(blk - BATCH*KPATCH) * DDIM;
        float4 v = ((const float4*)p)[t];
        float ss = v.x*v.x + v.y*v.y + v.z*v.z + v.w*v.w;
        #pragma unroll
        for (int o = 16; o; o >>= 1) ss += __shfl_xor_sync(0xffffffffu, ss, o);
        __shared__ float ws[8];
        if ((t & 31) == 0) ws[t >> 5] = ss;
        __syncthreads();
        if (t == 0) {
            float s = ws[0]+ws[1]+ws[2]+ws[3]+ws[4]+ws[5]+ws[6]+ws[7];
            float inv = 1.0f / sqrtf(s);
            if (blk < BATCH*KPATCH) g_fninv[blk] = inv;
            else                    g_eninv[blk - BATCH*KPATCH] = inv;
        }
    } else {
        // per-box branch: blk-NROWS = bn
        int bn = blk - NROWS;
        int x_min = boxes[bn*4+0], y_min = boxes[bn*4+1];
        int x_max = boxes[bn*4+2], y_max = boxes[bn*4+3];
        if (t < 2*PGRID) {
            int p, lo, hi;
            if (t < PGRID) { p = t;         lo = y_min; hi = y_max - 2; }
            else           { p = t - PGRID; lo = x_min; hi = x_max - 2; }
            float acc = 0.f;
            #pragma unroll 4
            for (int y = lo; y <= hi; ++y) acc += wnorm(y, p);
            if (t < PGRID) g_vy[bn*PGRID + p] = acc;
            else           g_vx[bn*PGRID + p] = acc;
        }
        if (t == 0) {
            float sfl = (y_min + 0.5f) * (1.0f/14.0f) - 0.5f;
            float sfh = (y_max - 2 + 0.5f) * (1.0f/14.0f) - 0.5f;
            int p0 = max(0, (int)floorf(sfl) - 1);
            int p1 = min(PGRID - 1, (int)floorf(sfh) + 2);
            sfl = (x_min + 0.5f) * (1.0f/14.0f) - 0.5f;
            sfh = (x_max - 2 + 0.5f) * (1.0f/14.0f) - 0.5f;
            int q0 = max(0, (int)floorf(sfl) - 1);
            int q1 = min(PGRID - 1, (int)floorf(sfh) + 2);
            g_rect[bn*4+0] = p0; g_rect[bn*4+1] = p1;
            g_rect[bn*4+2] = q0; g_rect[bn*4+3] = q1;
            float cnt = (float)((y_max - 1 - y_min) * (x_max - 1 - x_min));
            g_cntinv[bn] = __fdividef(1.0f, cnt);
        }
    }
}

// ---------------- kernel 2: Q[bn,d] = sum_k w[bn,k]/fn[b,k] * feats[b,k,d] ------
__global__ void __launch_bounds__(256) q_kernel(const float* __restrict__ feats) {
    int s  = blockIdx.x;       // 0..QSPLIT-1
    int bn = blockIdx.y;       // 0..63
    int b  = bn >> 5;
    int t  = threadIdx.x;

    __shared__ int   rect[4];
    __shared__ float vxs[16];
    if (t < 4) rect[t] = g_rect[bn*4+t];
    __syncthreads();
    int p0 = rect[0], p1 = rect[1], q0 = rect[2], q1 = rect[3];
    int nq = q1 - q0 + 1;      // <= 15
    if (t < 16) vxs[t] = (t < nq) ? g_vx[bn*PGRID + q0 + t] : 0.f;
    __syncthreads();

    int np  = p1 - p0 + 1;
    int plo = p0 + (np * s) / QSPLIT;
    int phi = p0 + (np * (s + 1)) / QSPLIT - 1;

    float4 acc = make_float4(0.f, 0.f, 0.f, 0.f);
    const float4* f4 = (const float4*)feats;

    for (int p = plo; p <= phi; ++p) {
        float wy = g_vy[bn*PGRID + p];
        int kbase = b*KPATCH + p*PGRID + q0;
        #pragma unroll
        for (int j = 0; j < 16; ++j) {
            int jj = min(j, nq - 1);                  // clamp address, weight is 0
            float w = wy * vxs[j] * g_fninv[kbase + jj];
            float4 f = f4[(size_t)(kbase + jj) * (DDIM/4) + t];
            acc.x += w * f.x; acc.y += w * f.y;
            acc.z += w * f.z; acc.w += w * f.w;
        }
    }
    ((float4*)g_Qpart)[(size_t)(s*BN + bn) * (DDIM/4) + t] = acc;
}

// ---------------- kernel 3: out += (Q @ embT) * cntinv  (atomic d-split) --------
// Qs: [bn][dd] (warp-broadcast reads). Es: [c][dd], 68-float row stride
// (phase-conflict-free LDS.128). d_out zeroed by cudaMemsetAsync at graph start;
// each d0-tile block atomically accumulates its partial, scaled by 1/count.
__global__ void __launch_bounds__(256) out_kernel(const float* __restrict__ emb,
                                                  float* __restrict__ out) {
    __shared__ float Qs[BN * 64];      // [bn][dd]  16KB
    __shared__ float Es[32 * 68];      // [c][dd]   8.5KB, stride 68
    int c0 = blockIdx.x * 32;
    int d0 = blockIdx.y * 64;
    int t  = threadIdx.x;

    // load Q tile: sum QSPLIT partials, float4-vectorized (1024 float4 total)
    const float4* qp4 = (const float4*)g_Qpart;
    #pragma unroll
    for (int i = 0; i < 4; ++i) {
        int lin = i * 256 + t;                 // 0..1023
        int bn = lin >> 4, dd4 = lin & 15;     // dd4: float4 index within 64 dd
        float4 v = make_float4(0.f,0.f,0.f,0.f);
        #pragma unroll
        for (int sp = 0; sp < QSPLIT; ++sp) {
            float4 a = qp4[(size_t)(sp*BN + bn) * (DDIM/4) + (d0>>2) + dd4];
            v.x += a.x; v.y += a.y; v.z += a.z; v.w += a.w;
        }
        ((float4*)Qs)[bn*16 + dd4] = v;
    }
    // load E tile (512 float4), scale by 1/||emb_c||
    const float4* e4 = (const float4*)emb;
    #pragma unroll
    for (int i = 0; i < 2; ++i) {
        int lin = i * 256 + t;                 // 0..511
        int c = lin >> 4, dd4 = lin & 15;
        float s = g_eninv[c0 + c];
        float4 a = e4[(size_t)(c0 + c) * (DDIM/4) + (d0>>2) + dd4];
        a.x *= s; a.y *= s; a.z *= s; a.w *= s;
        *(float4*)&Es[c*68 + dd4*4] = a;
    }
    __syncthreads();

    int c = t & 31, g = t >> 5;        // 8 bn-groups of 8
    float acc[8] = {0,0,0,0,0,0,0,0};
    #pragma unroll
    for (int dd4 = 0; dd4 < 16; ++dd4) {
        float4 e = *(const float4*)&Es[c*68 + dd4*4];
        #pragma unroll
        for (int j = 0; j < 8; ++j) {
            float4 q = ((const float4*)Qs)[(g*8 + j)*16 + dd4];   // broadcast
            acc[j] += q.x*e.x + q.y*e.y + q.z*e.z + q.w*e.w;
        }
    }
    #pragma unroll
    for (int j = 0; j < 8; ++j) {
        int bn = g*8 + j;
        atomicAdd(&out[bn*CCLS + c0 + c], acc[j] * g_cntinv[bn]);
    }
}

// ---------------- launch --------------------------------------------------------
extern "C" void kernel_launch(void* const* d_in, const int* in_sizes, int n_in,
                              void* d_out, int out_size) {
    (void)in_sizes; (void)n_in;
    const float* feats = (const float*)d_in[0];
    const float* emb   = (const float*)d_in[1];
    const int*   boxes = (const int*)d_in[2];
    float* out = (float*)d_out;

    cudaMemsetAsync(out, 0, (size_t)out_size * sizeof(float), 0);
    normbox_kernel<<<NROWS + BN, 256>>>(feats, emb, boxes);
    q_kernel<<<dim3(QSPLIT, BN), 256>>>(feats);
    out_kernel<<<dim3(CCLS/32, DDIM/64), 256>>>(emb, out);
}

// round 5
// speedup vs baseline: 3.1252x; 3.0434x over previous
#include <cuda_runtime.h>
#include <math.h>

#define BATCH  2
#define KPATCH 1600
#define DDIM   1024
#define CCLS   256
#define NBOX   32
#define PGRID  40
#define TARGET 560
#define BN     (BATCH*NBOX)            /* 64 */
#define NROWS  (BATCH*KPATCH + CCLS)   /* 3456 norm rows */
#define ROWS_PER_BLK 8
#define NORMBLKS (NROWS/ROWS_PER_BLK)  /* 432 */
#define QSPLIT 4

// ---------------- scratch (static device globals; no allocation) ----------------
__device__ float g_fninv[BATCH*KPATCH];     // 1/||feats[b,k,:]||
__device__ float g_eninv[CCLS];             // 1/||emb[c,:]||
__device__ float g_vy[BN*PGRID];            // per-box summed weights (y axis)
__device__ float g_vx[BN*PGRID];            // per-box summed weights (x axis)
__device__ int   g_rect[BN*4];              // p0,p1,q0,q1 nonzero tap rectangle
__device__ float g_cntinv[BN];              // 1/(box pixel count)
__device__ float g_Qpart[QSPLIT*BN*DDIM];   // partial weighted feature sums

// Keys cubic, a = -0.5 (matches jax.image.resize 'bicubic'), fp32
__device__ __forceinline__ float cubicf(float x) {   // x >= 0
    if (x < 1.f) return ((1.5f*x - 2.5f)*x)*x + 1.f;
    if (x < 2.f) return ((-0.5f*x + 2.5f)*x - 4.f)*x + 2.f;
    return 0.f;
}

// ------- kernel 1: warp-per-row L2 norms  +  per-pixel-parallel box taps --------
__global__ void __launch_bounds__(256) normbox_kernel(
        const float* __restrict__ feats,
        const float* __restrict__ emb,
        const int* __restrict__ boxes) {
    int blk  = blockIdx.x;
    int t    = threadIdx.x;
    int warp = t >> 5, lane = t & 31;

    if (blk < NORMBLKS) {
        // ---- norm branch: 8 rows per block, one warp each, MLP=8 ----
        int row = blk * ROWS_PER_BLK + warp;
        const float4* p4 = (row < BATCH*KPATCH)
                 ? (const float4*)(feats + (size_t)row * DDIM)
                 : (const float4*)(emb   + (size_t)(row - BATCH*KPATCH) * DDIM);
        float4 v[8];
        #pragma unroll
        for (int i = 0; i < 8; ++i) v[i] = p4[lane + 32*i];   // 8 independent LDG.128
        float ss = 0.f;
        #pragma unroll
        for (int i = 0; i < 8; ++i)
            ss += v[i].x*v[i].x + v[i].y*v[i].y + v[i].z*v[i].z + v[i].w*v[i].w;
        #pragma unroll
        for (int o = 16; o; o >>= 1) ss += __shfl_xor_sync(0xffffffffu, ss, o);
        if (lane == 0) {
            float inv = 1.0f / sqrtf(ss);
            if (row < BATCH*KPATCH) g_fninv[row] = inv;
            else                    g_eninv[row - BATCH*KPATCH] = inv;
        }
    } else {
        // ---- box branch: one block per box; parallel over output pixels ----
        int bn = blk - NORMBLKS;
        int x_min = boxes[bn*4+0], y_min = boxes[bn*4+1];
        int x_max = boxes[bn*4+2], y_max = boxes[bn*4+3];

        __shared__ float sv[2*PGRID];          // svy[0..39], svx[40..79]
        if (t < 2*PGRID) sv[t] = 0.f;
        __syncthreads();

        int ny = y_max - 1 - y_min;            // pixels y_min .. y_max-2
        int nx = x_max - 1 - x_min;
        for (int i = t; i < ny + nx; i += 256) {
            int y; float* dst;
            if (i < ny) { y = y_min + i;        dst = sv; }
            else        { y = x_min + (i - ny); dst = sv + PGRID; }
            float sf = (y + 0.5f) * (1.0f/14.0f) - 0.5f;
            int i0 = (int)floorf(sf);
            float w[4]; float cs = 0.f;
            #pragma unroll
            for (int j = 0; j < 4; ++j) {
                int ii = i0 - 1 + j;
                float c = (ii >= 0 && ii < PGRID) ? cubicf(fabsf(sf - (float)ii)) : 0.f;
                w[j] = c; cs += c;
            }
            float inv = __fdividef(1.0f, cs);
            #pragma unroll
            for (int j = 0; j < 4; ++j) {
                int ii = i0 - 1 + j;
                if (ii >= 0 && ii < PGRID && w[j] != 0.f)
                    atomicAdd(&dst[ii], w[j] * inv);
            }
        }
        __syncthreads();
        if (t < PGRID)            g_vy[bn*PGRID + t]           = sv[t];
        else if (t < 2*PGRID)     g_vx[bn*PGRID + (t - PGRID)] = sv[t];

        if (t == 0) {
            float sfl = (y_min + 0.5f) * (1.0f/14.0f) - 0.5f;
            float sfh = (y_max - 2 + 0.5f) * (1.0f/14.0f) - 0.5f;
            int p0 = max(0, (int)floorf(sfl) - 1);
            int p1 = min(PGRID - 1, (int)floorf(sfh) + 2);
            sfl = (x_min + 0.5f) * (1.0f/14.0f) - 0.5f;
            sfh = (x_max - 2 + 0.5f) * (1.0f/14.0f) - 0.5f;
            int q0 = max(0, (int)floorf(sfl) - 1);
            int q1 = min(PGRID - 1, (int)floorf(sfh) + 2);
            g_rect[bn*4+0] = p0; g_rect[bn*4+1] = p1;
            g_rect[bn*4+2] = q0; g_rect[bn*4+3] = q1;
            g_cntinv[bn] = __fdividef(1.0f, (float)(ny * nx));
        }
    }
}

// ---------------- kernel 2: Q[bn,d] = sum_k w[bn,k]/fn[b,k] * feats[b,k,d] ------
__global__ void __launch_bounds__(256) q_kernel(const float* __restrict__ feats) {
    int s  = blockIdx.x;       // 0..QSPLIT-1
    int bn = blockIdx.y;       // 0..63
    int b  = bn >> 5;
    int t  = threadIdx.x;

    __shared__ int   rect[4];
    __shared__ float vxs[16];
    if (t < 4) rect[t] = g_rect[bn*4+t];
    __syncthreads();
    int p0 = rect[0], p1 = rect[1], q0 = rect[2], q1 = rect[3];
    int nq = q1 - q0 + 1;      // <= 15
    if (t < 16) vxs[t] = (t < nq) ? g_vx[bn*PGRID + q0 + t] : 0.f;
    __syncthreads();

    int np  = p1 - p0 + 1;
    int plo = p0 + (np * s) / QSPLIT;
    int phi = p0 + (np * (s + 1)) / QSPLIT - 1;

    float4 acc = make_float4(0.f, 0.f, 0.f, 0.f);
    const float4* f4 = (const float4*)feats;

    for (int p = plo; p <= phi; ++p) {
        float wy = g_vy[bn*PGRID + p];
        int kbase = b*KPATCH + p*PGRID + q0;
        #pragma unroll
        for (int j = 0; j < 16; ++j) {
            int jj = min(j, nq - 1);                  // clamp address, weight is 0
            float w = wy * vxs[j] * g_fninv[kbase + jj];
            float4 f = f4[(size_t)(kbase + jj) * (DDIM/4) + t];
            acc.x += w * f.x; acc.y += w * f.y;
            acc.z += w * f.z; acc.w += w * f.w;
        }
    }
    ((float4*)g_Qpart)[(size_t)(s*BN + bn) * (DDIM/4) + t] = acc;
}

// ---------------- kernel 3: out += (Q @ embT) * cntinv  (atomic d-split) --------
__global__ void __launch_bounds__(256) out_kernel(const float* __restrict__ emb,
                                                  float* __restrict__ out) {
    __shared__ float Qs[BN * 64];      // [bn][dd]  16KB
    __shared__ float Es[32 * 68];      // [c][dd]   8.5KB, stride 68
    int c0 = blockIdx.x * 32;
    int d0 = blockIdx.y * 64;
    int t  = threadIdx.x;

    const float4* qp4 = (const float4*)g_Qpart;
    #pragma unroll
    for (int i = 0; i < 4; ++i) {
        int lin = i * 256 + t;                 // 0..1023
        int bn = lin >> 4, dd4 = lin & 15;
        float4 v = make_float4(0.f,0.f,0.f,0.f);
        #pragma unroll
        for (int sp = 0; sp < QSPLIT; ++sp) {
            float4 a = qp4[(size_t)(sp*BN + bn) * (DDIM/4) + (d0>>2) + dd4];
            v.x += a.x; v.y += a.y; v.z += a.z; v.w += a.w;
        }
        ((float4*)Qs)[bn*16 + dd4] = v;
    }
    const float4* e4 = (const float4*)emb;
    #pragma unroll
    for (int i = 0; i < 2; ++i) {
        int lin = i * 256 + t;                 // 0..511
        int c = lin >> 4, dd4 = lin & 15;
        float s = g_eninv[c0 + c];
        float4 a = e4[(size_t)(c0 + c) * (DDIM/4) + (d0>>2) + dd4];
        a.x *= s; a.y *= s; a.z *= s; a.w *= s;
        *(float4*)&Es[c*68 + dd4*4] = a;
    }
    __syncthreads();

    int c = t & 31, g = t >> 5;        // 8 bn-groups of 8
    float acc[8] = {0,0,0,0,0,0,0,0};
    #pragma unroll
    for (int dd4 = 0; dd4 < 16; ++dd4) {
        float4 e = *(const float4*)&Es[c*68 + dd4*4];
        #pragma unroll
        for (int j = 0; j < 8; ++j) {
            float4 q = ((const float4*)Qs)[(g*8 + j)*16 + dd4];   // broadcast
            acc[j] += q.x*e.x + q.y*e.y + q.z*e.z + q.w*e.w;
        }
    }
    #pragma unroll
    for (int j = 0; j < 8; ++j) {
        int bn = g*8 + j;
        atomicAdd(&out[bn*CCLS + c0 + c], acc[j] * g_cntinv[bn]);
    }
}

// ---------------- launch --------------------------------------------------------
extern "C" void kernel_launch(void* const* d_in, const int* in_sizes, int n_in,
                              void* d_out, int out_size) {
    (void)in_sizes; (void)n_in;
    const float* feats = (const float*)d_in[0];
    const float* emb   = (const float*)d_in[1];
    const int*   boxes = (const int*)d_in[2];
    float* out = (float*)d_out;

    cudaMemsetAsync(out, 0, (size_t)out_size * sizeof(float), 0);
    normbox_kernel<<<NORMBLKS + BN, 256>>>(feats, emb, boxes);
    q_kernel<<<dim3(QSPLIT, BN), 256>>>(feats);
    out_kernel<<<dim3(CCLS/32, DDIM/64), 256>>>(emb, out);
}